// round 17
// baseline (speedup 1.0000x reference)
#include <cuda_runtime.h>
#include <cstdint>
#include <cfloat>

// Problem constants (fixed by dataset)
#define NN    2048
#define TT    128
#define KSEL  20
#define MAXA  20
#define LRC   0.01f
#define EPSC  1e-8f
#define NW32  (NN/32)
#define PROWS 8            // sigma rows per panel block
#define NPAN  (NN/PROWS)   // 256 panel blocks
#define PSTR  2056         // padded panel row stride (floats)
#define OCAP  16           // occurrence list capacity

// ---------------- device scratch ---------------------------------------------
__device__ static int16_t  g_act_idx[TT * MAXA];
__device__ static int      g_act_cnt[TT];
__device__ static int      g_act_cntfull[TT];
__device__ static unsigned g_act_mask[TT * NW32];
__device__ static int      g_occ_cnt[NN];          // |{t<=126 : j in A(t)}|
__device__ static uint16_t g_occ[NN * OCAP];       // t | (m<<8)
__device__ static int      g_nxt_cnt[NN];          // |{s<=125 : i in A(s+1)}|
__device__ static uint16_t g_nxt[NN * OCAP];       // s
__device__ static float    g_pn2[TT - 1];
__device__ static float    g_dot[TT - 1];
__device__ static unsigned g_done2;

// ========= K1: top-K, one block/token, 1-pass 2048-bin radix + resolve =======
__global__ void __launch_bounds__(512)
k_topk(const int* __restrict__ tokens, const float* __restrict__ proj) {
    const int t    = blockIdx.x;
    const int tid  = threadIdx.x;
    const int lane = tid & 31;
    const int wid  = tid >> 5;

    __shared__ unsigned hist[2048];     // 8 KB
    __shared__ unsigned wsum[16];
    __shared__ unsigned cand[32];
    __shared__ unsigned smask[NW32];
    __shared__ unsigned s_bin, s_thr;
    __shared__ int      s_kk2, s_bc, s_nc, s_cnt;

    const float4 a = *reinterpret_cast<const float4*>(
        proj + (size_t)tokens[t] * NN + tid * 4);
    const float vv[4] = {a.x, a.y, a.z, a.w};
    unsigned key[4];
    #pragma unroll
    for (int m = 0; m < 4; m++) {
        const unsigned u = __float_as_uint(vv[m]);
        key[m] = (u >> 31) ? ~u : (u | 0x80000000u);   // monotone map
    }

    unsigned prefix = 0u, thr = 0u, Tlev = NN;
    int kkcur = KSEL;

    #pragma unroll
    for (int level = 0; level < 3; level++) {
        const int      SH = (level == 0) ? 21 : ((level == 1) ? 10 : 0);
        const int      WB = (level == 2) ? 10 : 11;
        const unsigned WM = (level == 2) ? 0x3FFu : 0x7FFu;

        reinterpret_cast<uint4*>(hist)[tid] = make_uint4(0u, 0u, 0u, 0u);
        __syncthreads();

        #pragma unroll
        for (int m = 0; m < 4; m++) {
            const bool part =
                (level == 0) || ((key[m] >> (SH + WB)) == prefix);
            const unsigned bin = part ? ((key[m] >> SH) & WM) : 0xFFFFu;
            const unsigned mk  = __match_any_sync(0xFFFFFFFFu, bin);
            if (part && lane == (__ffs(mk) - 1))
                atomicAdd(&hist[bin], (unsigned)__popc(mk));
        }
        __syncthreads();

        const uint4 h4 = reinterpret_cast<const uint4*>(hist)[tid];
        const unsigned hv[4] = {h4.x, h4.y, h4.z, h4.w};
        const unsigned lsum = hv[0] + hv[1] + hv[2] + hv[3];
        unsigned incl = lsum;
        #pragma unroll
        for (int o = 1; o < 32; o <<= 1) {
            const unsigned u = __shfl_up_sync(0xFFFFFFFFu, incl, o);
            if (lane >= o) incl += u;
        }
        if (lane == 31) wsum[wid] = incl;
        if (tid == 0) s_nc = 0;
        __syncthreads();
        unsigned woff = 0u;
        for (int q = 0; q < wid; q++) woff += wsum[q];
        unsigned e = woff + incl - lsum;
        const unsigned target = Tlev - (unsigned)kkcur;
        #pragma unroll
        for (int c = 0; c < 4; c++) {
            const unsigned hb = hv[c];
            if (hb && e <= target && target < e + hb) {
                s_bin = (unsigned)(tid * 4 + c);
                s_kk2 = kkcur - (int)(Tlev - e - hb);
                s_bc  = (int)hb;
            }
            e += hb;
        }
        __syncthreads();

        prefix = (prefix << WB) | s_bin;
        kkcur  = s_kk2;
        const int bc = s_bc;
        Tlev = (unsigned)bc;

        if (level == 2) { thr = prefix; break; }
        if (bc <= 32) {
            #pragma unroll
            for (int m = 0; m < 4; m++) {
                if ((key[m] >> SH) == prefix) {
                    const int p = atomicAdd(&s_nc, 1);
                    cand[p] = key[m];
                }
            }
            __syncthreads();
            if (tid < 32) {
                const int nc = s_nc;
                const unsigned c = (lane < nc) ? cand[lane] : 0u;
                int g = 0, eq = 0;
                for (int j = 0; j < nc; j++) {
                    const unsigned v = cand[j];
                    g  += (v > c);
                    eq += (v == c);
                }
                if (lane < nc && g < kkcur && kkcur <= g + eq) s_thr = c;
            }
            __syncthreads();
            thr = s_thr;
            break;
        }
    }

    if (tid < NW32) smask[tid] = 0u;
    if (tid == 0)   s_cnt = 0;
    __syncthreads();
    #pragma unroll
    for (int m = 0; m < 4; m++) {
        if (key[m] >= thr) {
            const int i = tid * 4 + m;
            atomicOr(&smask[i >> 5], 1u << (i & 31));
            const int p = atomicAdd(&s_cnt, 1);
            if (p < MAXA) g_act_idx[t * MAXA + p] = (int16_t)i;
        }
    }
    __syncthreads();
    const int cnt = s_cnt;
    const int cc  = (cnt < MAXA) ? cnt : MAXA;
    if (tid >= cc && tid < MAXA) g_act_idx[t * MAXA + tid] = 0;   // pad
    if (tid < NW32) g_act_mask[t * NW32 + tid] = smask[tid];
    if (tid == 0) { g_act_cntfull[t] = cnt; g_act_cnt[t] = cc; }
    __syncthreads();

    // ---- epilogue: accumulator reset + occurrence-list appends ----
    if (tid == 0 && t < TT - 1) { g_pn2[t] = 0.f; g_dot[t] = 0.f; }
    if (tid == 0 && t == TT - 1) g_done2 = 0u;
    if (tid < cc) {
        const int j = (int)g_act_idx[t * MAXA + tid];
        if (t <= TT - 2) {                      // occ: j in A(t), t in [0,126]
            const int slot = atomicAdd(&g_occ_cnt[j], 1);
            if (slot < OCAP)
                g_occ[j * OCAP + slot] = (uint16_t)(t | (tid << 8));
        }
        if (t >= 1 && t <= TT - 2) {            // nxt: i in A(s+1), s = t-1 <= 125
            const int slot = atomicAdd(&g_nxt_cnt[j], 1);
            if (slot < OCAP)
                g_nxt[j * OCAP + slot] = (uint16_t)(t - 1);
        }
    }
}

// ===== K2: 256 panel blocks; full pred (base+corr), partial pn2/dot, finisher =
// dynamic smem layout:
// panel 65792 @0 | idx 5120 @65792 | acnt 128 @70912 | cnt 20320 @71040
// pred 4096 @91360  -> total 95456
#define OFF_IDX   65792
#define OFF_ACNT  70912
#define OFF_CNT   71040
#define OFF_PRED  91360
#define SMEM_MID  95456

__global__ void __launch_bounds__(512)
k_mid(const float* __restrict__ S, const int* __restrict__ plast,
      float* __restrict__ out) {
    extern __shared__ __align__(16) char s_raw[];
    const int bx  = blockIdx.x;
    const int tid = threadIdx.x;
    const int i0  = bx * PROWS;

    float*    panel = reinterpret_cast<float*>(s_raw);
    int16_t*  idx   = reinterpret_cast<int16_t*>(s_raw + OFF_IDX);
    uint8_t*  acnt  = reinterpret_cast<uint8_t*>(s_raw + OFF_ACNT);
    unsigned* cntw  = reinterpret_cast<unsigned*>(s_raw + OFF_CNT);   // 5080 words
    float*    predp = reinterpret_cast<float*>(s_raw + OFF_PRED);     // [8][128]

    const int pl = *plast;

    // stage panel (8 sigma rows, coalesced float4)
    #pragma unroll
    for (int k = 0; k < 8; k++) {
        const int e   = k * 512 + tid;
        const int row = e >> 9;
        const int c4  = e & 511;
        const float4 sv = *reinterpret_cast<const float4*>(
            S + (size_t)(i0 + row) * NN + c4 * 4);
        *reinterpret_cast<float4*>(panel + row * PSTR + c4 * 4) = sv;
    }
    for (int x = tid; x < TT * MAXA / 2; x += 512)
        reinterpret_cast<int*>(idx)[x] = reinterpret_cast<const int*>(g_act_idx)[x];
    if (tid < TT) acnt[tid] = (uint8_t)g_act_cnt[tid];
    if (pl)
        for (int w = tid; w < 5080; w += 512) cntw[w] = 0u;
    __syncthreads();

    // base sums: thread owns (t, il); pred[il][t] = sum_{j in A(t)} panel[il][j]
    for (int p = tid; p < (TT - 1) * PROWS; p += 512) {
        const int t  = p >> 3;
        const int il = p & 7;
        const int cnt = (int)acnt[t];
        const float* prow = panel + il * PSTR;
        float sum = 0.f;
        #pragma unroll
        for (int m = 0; m < MAXA; m++) {
            const float v = prow[(int)idx[t * MAXA + m]];
            if (m < cnt) sum += v;
        }
        predp[il * TT + t] = sum;
    }

    // event counting: for i in panel, s in nxt(i), j in A(s), (t,m) in occ(j), t>s
    if (pl && tid < PROWS * OCAP) {
        const int il = tid >> 4;
        const int e  = tid & (OCAP - 1);
        const int i  = i0 + il;
        int nn = g_nxt_cnt[i]; if (nn > OCAP) nn = OCAP;
        if (e < nn) {
            const int s  = (int)g_nxt[i * OCAP + e];
            const int ca = (int)acnt[s];
            for (int m = 0; m < ca; m++) {
                const int j = (int)idx[s * MAXA + m];
                int oc = g_occ_cnt[j]; if (oc > OCAP) oc = OCAP;
                for (int f = 0; f < oc; f++) {
                    const unsigned pk = g_occ[j * OCAP + f];
                    const int t2 = (int)(pk & 0xFFu);
                    if (t2 > s) {
                        const unsigned off =
                            (unsigned)il * 2540u + (unsigned)t2 * 20u + (pk >> 8);
                        atomicAdd(&cntw[off >> 2], 1u << ((off & 3u) * 8u));
                    }
                }
            }
        }
    }
    __syncthreads();

    // apply clip corrections (rare nonzero counters)
    if (pl) {
        for (int w = tid; w < 5080; w += 512) {
            const unsigned word = cntw[w];
            if (word) {
                const int il = w / 635;
                const int r  = w - il * 635;
                const float* prow = panel + il * PSTR;
                #pragma unroll
                for (int b = 0; b < 4; b++) {
                    const unsigned c = (word >> (b * 8)) & 0xFFu;
                    if (c) {
                        const int e2 = r * 4 + b;
                        const int t2 = e2 / 20;
                        const int m  = e2 - t2 * 20;
                        const float v = prow[(int)idx[t2 * MAXA + m]];
                        atomicAdd(&predp[il * TT + t2],
                                  fminf(v + LRC * (float)c, 1.0f) - v);
                    }
                }
            }
        }
    }
    __syncthreads();

    // per-t partial reduction over this panel's 8 i's -> global accumulators
    if (tid < TT - 1) {
        const int t = tid;
        const unsigned mword = g_act_mask[(t + 1) * NW32 + (i0 >> 5)];
        const int bb = i0 & 31;
        float pn2 = 0.f, dt = 0.f;
        #pragma unroll
        for (int il = 0; il < PROWS; il++) {
            const float f = predp[il * TT + t];
            pn2 += f * f;
            if ((mword >> (bb + il)) & 1u) dt += f;
        }
        atomicAdd(&g_pn2[t], pn2);
        atomicAdd(&g_dot[t], dt);
    }

    // finisher: last block computes tensions + resets occurrence counters
    __threadfence();
    __syncthreads();
    __shared__ int s_last;
    if (tid == 0) {
        const unsigned tk = atomicAdd(&g_done2, 1u);
        s_last = (tk == NPAN - 1u);
    }
    __syncthreads();
    if (s_last) {
        __threadfence();
        if (tid < TT - 1) {
            float P2, D;
            asm volatile("ld.volatile.global.f32 %0, [%1];"
                         : "=f"(P2) : "l"(&g_pn2[tid]));
            asm volatile("ld.volatile.global.f32 %0, [%1];"
                         : "=f"(D) : "l"(&g_dot[tid]));
            const float pn = sqrtf(P2);
            float tension;
            if (pl) {
                const float overlap = D / (pn * sqrtf((float)KSEL) + EPSC);
                tension = (pn > 0.0f) ? (1.0f - overlap) : 1.0f;
            } else {
                const float xn = sqrtf((float)g_act_cntfull[tid + 1]);
                tension = 1.0f - D / (pn * xn + EPSC);
            }
            out[tid] = tension;
        }
        // reset occurrence counters for next replay (self-maintaining)
        for (int x = tid; x < NN; x += 512) {
            g_occ_cnt[x] = 0;
            g_nxt_cnt[x] = 0;
        }
    }
}

// ---------------- launch ------------------------------------------------------
extern "C" void kernel_launch(void* const* d_in, const int* in_sizes, int n_in,
                              void* d_out, int out_size) {
    const int*   tokens = (const int*)d_in[0];
    const float* proj   = (const float*)d_in[1];
    const float* sigma  = (const float*)d_in[2];
    const int*   plast  = (const int*)d_in[3];
    float*       out    = (float*)d_out;

    static int smem_set = 0;
    if (!smem_set) {
        cudaFuncSetAttribute(k_mid, cudaFuncAttributeMaxDynamicSharedMemorySize,
                             SMEM_MID);
        smem_set = 1;
    }
    k_topk<<<TT, 512>>>(tokens, proj);
    k_mid<<<NPAN, 512, SMEM_MID>>>(sigma, plast, out);
}